// round 5
// baseline (speedup 1.0000x reference)
#include <cuda_runtime.h>
#include <cuda_fp16.h>

// SmileMoENorm — R4 (packed-fp16 affine) + occupancy boost.
//
// R4 hit 83% DRAM with occ=43.5% (56 regs; the v[8] row cache costs 32).
// This version caches only HALF the row in registers and re-reads the other
// half in the epilogue (L1/L2 hit — the row was fetched moments earlier).
// __launch_bounds__(256,6) caps regs at 42 -> 48 warps/SM, smoothing the
// DRAM request stream. L1/L2 absorb the extra re-read (both have headroom).

#define N_TOKENS    131072
#define HIDDEN      1024
#define NUM_EXPERTS 8
#define H4          (HIDDEN / 4)
#define EPS         1e-5f

__device__ __half2 d_pk[NUM_EXPERTS * HIDDEN];   // (gamma, beta) per element

// ---- pre-pass: pack gamma/beta into fp16 ----------------------------------
__global__ void k_pack(const float* __restrict__ gamma,
                       const float* __restrict__ beta) {
    const int i = blockIdx.x * blockDim.x + threadIdx.x;   // 0..8191
    d_pk[i] = __floats2half2_rn(gamma[i], beta[i]);
}

// ------------------------------------------------------------- main kernel
__global__ __launch_bounds__(256, 6)
void smile_moe_norm_kernel(const float4* __restrict__ x,
                           const float4* __restrict__ logits4,   // [N,2] float4
                           float4* __restrict__ out) {
    const int warp_in_block = threadIdx.x >> 5;
    const int lane          = threadIdx.x & 31;
    const int token         = blockIdx.x * (blockDim.x >> 5) + warp_in_block;
    if (token >= N_TOKENS) return;

    // ---- router: top-2 of 8 logits, renormalized softmax weights ----------
    const float4 la = logits4[token * 2 + 0];
    const float4 lb = logits4[token * 2 + 1];
    float l[NUM_EXPERTS] = { la.x, la.y, la.z, la.w, lb.x, lb.y, lb.z, lb.w };

    float best = l[0], second = -3.4e38f;
    int   e0 = 0,     e1 = 0;
    #pragma unroll
    for (int i = 1; i < NUM_EXPERTS; i++) {
        float v = l[i];
        if (v > best)        { second = best; e1 = e0; best = v; e0 = i; }
        else if (v > second) { second = v; e1 = i; }
    }
    const float t  = __expf(second - best);     // full-softmax denom cancels
    const float w0 = 1.0f / (1.0f + t);
    const float w1 = 1.0f - w0;
    const __half2 w0h = __float2half2_rn(w0);
    const __half2 w1h = __float2half2_rn(w1);

    // ---- stats pass: cache first half in regs, stream second half ----------
    const float4* xr = x + (size_t)token * H4;
    float sum = 0.0f, sq = 0.0f;
    float4 v[4];
    #pragma unroll
    for (int k = 0; k < 4; k++) {
        v[k] = xr[lane + 32 * k];
        sum += v[k].x + v[k].y + v[k].z + v[k].w;
        sq = fmaf(v[k].x, v[k].x, sq); sq = fmaf(v[k].y, v[k].y, sq);
        sq = fmaf(v[k].z, v[k].z, sq); sq = fmaf(v[k].w, v[k].w, sq);
    }
    #pragma unroll
    for (int k = 4; k < 8; k++) {
        const float4 tv = xr[lane + 32 * k];
        sum += tv.x + tv.y + tv.z + tv.w;
        sq = fmaf(tv.x, tv.x, sq); sq = fmaf(tv.y, tv.y, sq);
        sq = fmaf(tv.z, tv.z, sq); sq = fmaf(tv.w, tv.w, sq);
    }
    #pragma unroll
    for (int off = 16; off > 0; off >>= 1) {
        sum += __shfl_xor_sync(0xFFFFFFFFu, sum, off);
        sq  += __shfl_xor_sync(0xFFFFFFFFu, sq,  off);
    }
    const float mean = sum * (1.0f / HIDDEN);
    const float var  = fmaf(-mean, mean, sq * (1.0f / HIDDEN));
    const float rstd = rsqrtf(var + EPS);
    const float mr   = -mean * rstd;            // normed = x*rstd + mr

    // ---- apply pass: packed-fp16 blended affine + store ---------------------
    const __half2* pk0 = d_pk + e0 * HIDDEN;
    const __half2* pk1 = d_pk + e1 * HIDDEN;
    float4* orow = out + (size_t)token * H4;

    #pragma unroll
    for (int k = 0; k < 8; k++) {
        const int h4 = lane + 32 * k;           // float4 index
        const int h  = 4 * h4;                  // element index
        const float4 xv = (k < 4) ? v[k] : xr[h4];   // re-read = L1/L2 hit
        const uint4 r0 = *(const uint4*)(pk0 + h);
        const uint4 r1 = *(const uint4*)(pk1 + h);

        const float nx = fmaf(xv.x, rstd, mr);
        const float ny = fmaf(xv.y, rstd, mr);
        const float nz = fmaf(xv.z, rstd, mr);
        const float nw = fmaf(xv.w, rstd, mr);

        __half2 a, b; float2 fb; float4 o;
        a = *(const __half2*)&r0.x; b = *(const __half2*)&r1.x;
        fb = __half22float2(__hfma2(a, w0h, __hmul2(b, w1h)));
        o.x = fmaf(nx, fb.x, fb.y);

        a = *(const __half2*)&r0.y; b = *(const __half2*)&r1.y;
        fb = __half22float2(__hfma2(a, w0h, __hmul2(b, w1h)));
        o.y = fmaf(ny, fb.x, fb.y);

        a = *(const __half2*)&r0.z; b = *(const __half2*)&r1.z;
        fb = __half22float2(__hfma2(a, w0h, __hmul2(b, w1h)));
        o.z = fmaf(nz, fb.x, fb.y);

        a = *(const __half2*)&r0.w; b = *(const __half2*)&r1.w;
        fb = __half22float2(__hfma2(a, w0h, __hmul2(b, w1h)));
        o.w = fmaf(nw, fb.x, fb.y);

        orow[h4] = o;
    }
}

// ------------------------------------------------------------------ launch
extern "C" void kernel_launch(void* const* d_in, const int* in_sizes, int n_in,
                              void* d_out, int out_size) {
    const float4* x       = (const float4*)d_in[0];  // hidden_states [N, H]
    const float4* logits4 = (const float4*)d_in[1];  // router_logits [N, 8]
    const float*  gamma   = (const float*)d_in[2];   // [E, H]
    const float*  beta    = (const float*)d_in[3];   // [E, H]
    float4* out           = (float4*)d_out;

    k_pack<<<(NUM_EXPERTS * HIDDEN) / 256, 256>>>(gamma, beta);

    const int warps_per_block = 8;                   // 256 threads
    const int blocks = N_TOKENS / warps_per_block;   // 16384
    smile_moe_norm_kernel<<<blocks, warps_per_block * 32>>>(x, logits4, out);
}

// round 6
// speedup vs baseline: 1.1101x; 1.1101x over previous
#include <cuda_runtime.h>
#include <cuda_fp16.h>

// SmileMoENorm — R4 (packed-fp16 affine, full-row register cache) + PDL +
// streaming cache hints.
//
// R5 taught: occupancy beyond 32 warps/SM hurts (re-reads blow L1; DRAM%
// drops). So keep R4's single-read v[8] structure exactly. Two new levers:
//  (a) PDL: main kernel launches concurrently with k_pack and only
//      cudaGridDependencySynchronize()s right before its epilogue touches
//      d_pk — hides the ~5.7us serial pack+launch gap.
//  (b) __ldcs on x / __stcs on out: both are touch-once streams; keep them
//      out of L2's way so the d_pk/logits working set stays resident.

#define N_TOKENS    131072
#define HIDDEN      1024
#define NUM_EXPERTS 8
#define H4          (HIDDEN / 4)
#define EPS         1e-5f

__device__ __half2 d_pk[NUM_EXPERTS * HIDDEN];   // (gamma, beta) per element

// ---- pre-pass: pack gamma/beta into fp16 ----------------------------------
__global__ void k_pack(const float* __restrict__ gamma,
                       const float* __restrict__ beta) {
    const int i = blockIdx.x * blockDim.x + threadIdx.x;   // 0..8191
    d_pk[i] = __floats2half2_rn(gamma[i], beta[i]);
}

// ------------------------------------------------------------- main kernel
__global__ __launch_bounds__(256, 4)
void smile_moe_norm_kernel(const float4* __restrict__ x,
                           const float4* __restrict__ logits4,   // [N,2] float4
                           float4* __restrict__ out) {
    const int warp_in_block = threadIdx.x >> 5;
    const int lane          = threadIdx.x & 31;
    const int token         = blockIdx.x * (blockDim.x >> 5) + warp_in_block;

    // ---- router: top-2 of 8 logits, renormalized softmax weights ----------
    const float4 la = __ldg(&logits4[token * 2 + 0]);
    const float4 lb = __ldg(&logits4[token * 2 + 1]);
    float l[NUM_EXPERTS] = { la.x, la.y, la.z, la.w, lb.x, lb.y, lb.z, lb.w };

    float best = l[0], second = -3.4e38f;
    int   e0 = 0,     e1 = 0;
    #pragma unroll
    for (int i = 1; i < NUM_EXPERTS; i++) {
        float v = l[i];
        if (v > best)        { second = best; e1 = e0; best = v; e0 = i; }
        else if (v > second) { second = v; e1 = i; }
    }
    const float t  = __expf(second - best);     // full-softmax denom cancels
    const float w0 = 1.0f / (1.0f + t);
    const float w1 = 1.0f - w0;
    const __half2 w0h = __float2half2_rn(w0);
    const __half2 w1h = __float2half2_rn(w1);

    // ---- pass over row: registers + warp reduction (streaming loads) -------
    const float4* xr = x + (size_t)token * H4;
    float4 v[8];
    float sum = 0.0f, sq = 0.0f;
    #pragma unroll
    for (int k = 0; k < 8; k++) {
        v[k] = __ldcs(&xr[lane + 32 * k]);      // touch-once: evict-first
        sum += v[k].x + v[k].y + v[k].z + v[k].w;
        sq = fmaf(v[k].x, v[k].x, sq); sq = fmaf(v[k].y, v[k].y, sq);
        sq = fmaf(v[k].z, v[k].z, sq); sq = fmaf(v[k].w, v[k].w, sq);
    }
    #pragma unroll
    for (int off = 16; off > 0; off >>= 1) {
        sum += __shfl_xor_sync(0xFFFFFFFFu, sum, off);
        sq  += __shfl_xor_sync(0xFFFFFFFFu, sq,  off);
    }
    const float mean = sum * (1.0f / HIDDEN);
    const float var  = fmaf(-mean, mean, sq * (1.0f / HIDDEN));
    const float rstd = rsqrtf(var + EPS);
    const float mr   = -mean * rstd;            // normed = x*rstd + mr

    // PDL: d_pk is written by k_pack; wait for it only now (hidden latency).
    cudaGridDependencySynchronize();

    // ---- epilogue: packed-fp16 blended affine + streaming store -------------
    const __half2* pk0 = d_pk + e0 * HIDDEN;
    const __half2* pk1 = d_pk + e1 * HIDDEN;
    float4* orow = out + (size_t)token * H4;

    #pragma unroll
    for (int k = 0; k < 8; k++) {
        const int h4 = lane + 32 * k;           // float4 index
        const int h  = 4 * h4;                  // element index
        const uint4 r0 = *(const uint4*)(pk0 + h);
        const uint4 r1 = *(const uint4*)(pk1 + h);

        const float nx = fmaf(v[k].x, rstd, mr);
        const float ny = fmaf(v[k].y, rstd, mr);
        const float nz = fmaf(v[k].z, rstd, mr);
        const float nw = fmaf(v[k].w, rstd, mr);

        __half2 a, b; float2 fb; float4 o;
        a = *(const __half2*)&r0.x; b = *(const __half2*)&r1.x;
        fb = __half22float2(__hfma2(a, w0h, __hmul2(b, w1h)));
        o.x = fmaf(nx, fb.x, fb.y);

        a = *(const __half2*)&r0.y; b = *(const __half2*)&r1.y;
        fb = __half22float2(__hfma2(a, w0h, __hmul2(b, w1h)));
        o.y = fmaf(ny, fb.x, fb.y);

        a = *(const __half2*)&r0.z; b = *(const __half2*)&r1.z;
        fb = __half22float2(__hfma2(a, w0h, __hmul2(b, w1h)));
        o.z = fmaf(nz, fb.x, fb.y);

        a = *(const __half2*)&r0.w; b = *(const __half2*)&r1.w;
        fb = __half22float2(__hfma2(a, w0h, __hmul2(b, w1h)));
        o.w = fmaf(nw, fb.x, fb.y);

        __stcs(&orow[h4], o);                   // streaming store
    }
}

// ------------------------------------------------------------------ launch
extern "C" void kernel_launch(void* const* d_in, const int* in_sizes, int n_in,
                              void* d_out, int out_size) {
    const float4* x       = (const float4*)d_in[0];  // hidden_states [N, H]
    const float4* logits4 = (const float4*)d_in[1];  // router_logits [N, 8]
    const float*  gamma   = (const float*)d_in[2];   // [E, H]
    const float*  beta    = (const float*)d_in[3];   // [E, H]
    float4* out           = (float4*)d_out;

    k_pack<<<(NUM_EXPERTS * HIDDEN) / 256, 256>>>(gamma, beta);

    // Main kernel with programmatic dependent launch: overlaps with k_pack;
    // the in-kernel cudaGridDependencySynchronize() provides the ordering.
    cudaLaunchConfig_t cfg = {};
    cfg.gridDim  = dim3(N_TOKENS / 8, 1, 1);         // 8 warps/block
    cfg.blockDim = dim3(256, 1, 1);
    cudaLaunchAttribute attr[1];
    attr[0].id = cudaLaunchAttributeProgrammaticStreamSerialization;
    attr[0].val.programmaticStreamSerializationAllowed = 1;
    cfg.attrs = attr;
    cfg.numAttrs = 1;
    cudaLaunchKernelEx(&cfg, smile_moe_norm_kernel, x, logits4, out);
}